// round 2
// baseline (speedup 1.0000x reference)
#include <cuda_runtime.h>
#include <cstdint>

// Problem constants
#define NB   4
#define NS_N 10000
#define NT_N 10000
#define NE   160000
#define NK   16
#define ND   128
#define LDA  136                         // smem row stride (pad 8 -> conflict-free frags)
#define SMEM_BYTES (2 * 128 * LDA * 4)   // 139264 B: A tile + B tile

// Scratch (static device allocs are allowed; cudaMalloc is not)
__device__ float g_Ps[(size_t)NB * NS_N * ND];
__device__ float g_Pt[(size_t)NB * NT_N * ND];
__device__ float g_dbond[(size_t)NB * NE * ND];
__device__ float g_bred[(size_t)NB * NT_N * ND];

__device__ __forceinline__ unsigned f2tf(float f) {
    unsigned r;
    asm("cvt.rna.tf32.f32 %0, %1;" : "=r"(r) : "f"(f));
    return r;
}

__device__ __forceinline__ void mma8(float c[4], const unsigned a[4], const unsigned b[2]) {
    asm volatile(
        "mma.sync.aligned.m16n8k8.row.col.f32.tf32.tf32.f32 "
        "{%0,%1,%2,%3},{%4,%5,%6,%7},{%8,%9},{%0,%1,%2,%3};"
        : "+f"(c[0]), "+f"(c[1]), "+f"(c[2]), "+f"(c[3])
        : "r"(a[0]), "r"(a[1]), "r"(a[2]), "r"(a[3]), "r"(b[0]), "r"(b[1]));
}

// Load a 128x128 fp32 tile (raw, NO tf32 truncation -> epilogue can reuse exact values)
__device__ __forceinline__ void load_tile_raw(float* Ash, const float* __restrict__ A,
                                              long row0, long M, int tid) {
    #pragma unroll
    for (int t = tid; t < 128 * 32; t += 256) {
        int r = t >> 5, c4 = (t & 31) << 2;
        float4 v = make_float4(0.f, 0.f, 0.f, 0.f);
        long rr = row0 + r;
        if (rr < M) v = *(const float4*)(A + rr * (long)ND + c4);
        *(float4*)(Ash + r * LDA + c4) = v;
    }
}

// Load 128x128 weight tile, rounding to tf32 once (rna)
__device__ __forceinline__ void load_w_tf32(float* Bsh, const float* __restrict__ W, int tid) {
    #pragma unroll
    for (int t = tid; t < 128 * 32; t += 256) {
        int r = t >> 5, c4 = (t & 31) << 2;
        float4 v = *(const float4*)(W + r * ND + c4);
        v.x = __uint_as_float(f2tf(v.x));
        v.y = __uint_as_float(f2tf(v.y));
        v.z = __uint_as_float(f2tf(v.z));
        v.w = __uint_as_float(f2tf(v.w));
        *(float4*)(Bsh + r * LDA + c4) = v;
    }
}

// 128x128x128 tile GEMM. 8 warps in 4(M) x 2(N) grid; warp tile 32x64.
__device__ __forceinline__ void gemm_tile(const float* Ash, const float* Bsh,
                                          float c[2][8][4], int wm, int wn, int lane) {
    int lr = lane >> 2, lc = lane & 3;
    for (int kk = 0; kk < 16; ++kk) {
        int k0 = kk * 8;
        unsigned a[2][4];
        #pragma unroll
        for (int i = 0; i < 2; ++i) {
            int m0 = wm * 32 + i * 16 + lr;
            a[i][0] = f2tf(Ash[m0 * LDA + k0 + lc]);
            a[i][1] = f2tf(Ash[(m0 + 8) * LDA + k0 + lc]);
            a[i][2] = f2tf(Ash[m0 * LDA + k0 + 4 + lc]);
            a[i][3] = f2tf(Ash[(m0 + 8) * LDA + k0 + 4 + lc]);
        }
        unsigned b[8][2];
        #pragma unroll
        for (int j = 0; j < 8; ++j) {
            int n0 = wn * 64 + j * 8 + lr;
            b[j][0] = __float_as_uint(Bsh[(k0 + lc) * LDA + n0]);
            b[j][1] = __float_as_uint(Bsh[(k0 + 4 + lc) * LDA + n0]);
        }
        #pragma unroll
        for (int i = 0; i < 2; ++i)
            #pragma unroll
            for (int j = 0; j < 8; ++j)
                mma8(c[i][j], a[i], b[j]);
    }
}

__device__ __forceinline__ void stage_acc(float* Csh, float c[2][8][4], int wm, int wn, int lane) {
    int lr = lane >> 2, lc = lane & 3;
    #pragma unroll
    for (int i = 0; i < 2; ++i)
        #pragma unroll
        for (int j = 0; j < 8; ++j) {
            int r = wm * 32 + i * 16 + lr;
            int col = wn * 64 + j * 8 + (lc << 1);
            *(float2*)(Csh + r * LDA + col)       = make_float2(c[i][j][0], c[i][j][1]);
            *(float2*)(Csh + (r + 8) * LDA + col) = make_float2(c[i][j][2], c[i][j][3]);
        }
}

__device__ __forceinline__ float silu_f(float x) { return x / (1.f + __expf(-x)); }

__device__ __forceinline__ void zero_acc(float c[2][8][4]) {
    #pragma unroll
    for (int i = 0; i < 2; ++i)
        #pragma unroll
        for (int j = 0; j < 8; ++j)
            #pragma unroll
            for (int q = 0; q < 4; ++q) c[i][j][q] = 0.f;
}

// ---------------------------------------------------------------------------
// K1: P_s = src @ W_s2e ; P_t = tgt @ W_t2e    (blockIdx.y selects)
// ---------------------------------------------------------------------------
__global__ __launch_bounds__(256) void proj_kernel(const float* __restrict__ src,
                                                   const float* __restrict__ tgt,
                                                   const float* __restrict__ Ws,
                                                   const float* __restrict__ Wt) {
    extern __shared__ float sm[];
    float* Ash = sm;
    float* Bsh = sm + 128 * LDA;
    const float* A;
    const float* W;
    float* O;
    if (blockIdx.y == 0) { A = src; W = Ws; O = g_Ps; }
    else                 { A = tgt; W = Wt; O = g_Pt; }
    long row0 = (long)blockIdx.x * 128;
    const long M = (long)NB * NS_N;
    int tid = threadIdx.x, lane = tid & 31, wid = tid >> 5, wm = wid & 3, wn = wid >> 2;

    load_tile_raw(Ash, A, row0, M, tid);
    load_w_tf32(Bsh, W, tid);
    __syncthreads();

    float c[2][8][4];
    zero_acc(c);
    gemm_tile(Ash, Bsh, c, wm, wn, lane);

    int lr = lane >> 2, lc = lane & 3;
    #pragma unroll
    for (int i = 0; i < 2; ++i)
        #pragma unroll
        for (int j = 0; j < 8; ++j) {
            long r = row0 + wm * 32 + i * 16 + lr;
            int col = wn * 64 + j * 8 + (lc << 1);
            if (r < M)     *(float2*)(O + r * ND + col)       = make_float2(c[i][j][0], c[i][j][1]);
            if (r + 8 < M) *(float2*)(O + (r + 8) * ND + col) = make_float2(c[i][j][2], c[i][j][3]);
        }
}

// ---------------------------------------------------------------------------
// K2: d_bond = LN(silu(bond@W_e2e + gather(P_s) + gather(P_t)));
//     out0 = bond + d_bond;  d_bond -> scratch
// ---------------------------------------------------------------------------
__global__ __launch_bounds__(256) void edge_kernel(const float* __restrict__ bond,
                                                   const float* __restrict__ We2e,
                                                   const float* __restrict__ lng,
                                                   const float* __restrict__ lnb,
                                                   const int* __restrict__ src_order,
                                                   const int* __restrict__ tgt_order,
                                                   float* __restrict__ out0) {
    extern __shared__ float sm[];
    float* Ash = sm;
    float* Bsh = sm + 128 * LDA;
    long row0 = (long)blockIdx.x * 128;  // rows over B*E (E % 128 == 0, no batch straddle)
    int tid = threadIdx.x, lane = tid & 31, wid = tid >> 5, wm = wid & 3, wn = wid >> 2;

    load_tile_raw(Ash, bond, row0, (long)NB * NE, tid);
    load_w_tf32(Bsh, We2e, tid);
    __syncthreads();

    float c[2][8][4];
    zero_acc(c);
    gemm_tile(Ash, Bsh, c, wm, wn, lane);
    __syncthreads();               // everyone done reading Bsh
    stage_acc(Bsh, c, wm, wn, lane);
    __syncthreads();

    int cc = lane << 2;
    #pragma unroll 1
    for (int r = wid * 16; r < wid * 16 + 16; ++r) {
        long e = row0 + r;
        int b = (int)(e / NE);
        int el = (int)(e - (long)b * NE);
        int si = __ldg(src_order + el);
        int ti = __ldg(tgt_order + el);
        float4 v  = *(float4*)(Bsh + r * LDA + cc);
        float4 ps = *(const float4*)(g_Ps + ((long)b * NS_N + si) * ND + cc);
        float4 pt = *(const float4*)(g_Pt + ((long)b * NT_N + ti) * ND + cc);
        float x0 = silu_f(v.x + ps.x + pt.x);
        float x1 = silu_f(v.y + ps.y + pt.y);
        float x2 = silu_f(v.z + ps.z + pt.z);
        float x3 = silu_f(v.w + ps.w + pt.w);
        float s = x0 + x1 + x2 + x3;
        float q = x0 * x0 + x1 * x1 + x2 * x2 + x3 * x3;
        #pragma unroll
        for (int o = 16; o > 0; o >>= 1) {
            s += __shfl_xor_sync(0xffffffffu, s, o);
            q += __shfl_xor_sync(0xffffffffu, q, o);
        }
        float mean = s * (1.f / ND);
        float var  = q * (1.f / ND) - mean * mean;
        float rstd = rsqrtf(var + 1e-5f);
        float4 gg = *(const float4*)(lng + cc);
        float4 bb = *(const float4*)(lnb + cc);
        float y0 = (x0 - mean) * rstd * gg.x + bb.x;
        float y1 = (x1 - mean) * rstd * gg.y + bb.y;
        float y2 = (x2 - mean) * rstd * gg.z + bb.z;
        float y3 = (x3 - mean) * rstd * gg.w + bb.w;
        long off = e * ND + cc;
        *(float4*)(g_dbond + off) = make_float4(y0, y1, y2, y3);
        float4 bd = *(float4*)(Ash + r * LDA + cc);  // exact fp32 bond value
        *(float4*)(out0 + off) = make_float4(bd.x + y0, bd.y + y1, bd.z + y2, bd.w + y3);
    }
}

// ---------------------------------------------------------------------------
// K3: bond_reduce[b,nt,:] = (1/K) * sum_k coef[nt,k] * d_bond[b, edge_order[nt,k], :]
// ---------------------------------------------------------------------------
__global__ __launch_bounds__(128) void gather_kernel(const int* __restrict__ edge_order,
                                                     const float* __restrict__ coef) {
    int bn = blockIdx.x;                 // 0 .. B*NT-1
    int b = bn / NT_N, nt = bn - b * NT_N;
    __shared__ int   eo[NK];
    __shared__ float cf[NK];
    if (threadIdx.x < NK) {
        eo[threadIdx.x] = edge_order[nt * NK + threadIdx.x];
        cf[threadIdx.x] = coef[nt * NK + threadIdx.x];
    }
    __syncthreads();
    int d = threadIdx.x;
    const float* base = g_dbond + (long)b * NE * ND;
    float acc = 0.f;
    #pragma unroll
    for (int k = 0; k < NK; ++k)
        acc += cf[k] * __ldg(base + (long)eo[k] * ND + d);
    g_bred[(long)bn * ND + d] = acc * (1.f / NK);
}

// ---------------------------------------------------------------------------
// K4: out2 = tgt + LN(silu(bond_reduce@W_e2t + tgt@W_t2t))
// ---------------------------------------------------------------------------
__global__ __launch_bounds__(256) void tgt_kernel(const float* __restrict__ tgt,
                                                  const float* __restrict__ We2t,
                                                  const float* __restrict__ Wt2t,
                                                  const float* __restrict__ lng,
                                                  const float* __restrict__ lnb,
                                                  float* __restrict__ out2) {
    extern __shared__ float sm[];
    float* Ash = sm;
    float* Bsh = sm + 128 * LDA;
    long row0 = (long)blockIdx.x * 128;
    const long M = (long)NB * NT_N;
    int tid = threadIdx.x, lane = tid & 31, wid = tid >> 5, wm = wid & 3, wn = wid >> 2;

    float c[2][8][4];
    zero_acc(c);

    load_tile_raw(Ash, g_bred, row0, M, tid);
    load_w_tf32(Bsh, We2t, tid);
    __syncthreads();
    gemm_tile(Ash, Bsh, c, wm, wn, lane);
    __syncthreads();

    load_tile_raw(Ash, tgt, row0, M, tid);   // Ash ends holding exact tgt for the residual
    load_w_tf32(Bsh, Wt2t, tid);
    __syncthreads();
    gemm_tile(Ash, Bsh, c, wm, wn, lane);
    __syncthreads();
    stage_acc(Bsh, c, wm, wn, lane);
    __syncthreads();

    int cc = lane << 2;
    #pragma unroll 1
    for (int r = wid * 16; r < wid * 16 + 16; ++r) {
        long e = row0 + r;
        if (e >= M) break;
        float4 v = *(float4*)(Bsh + r * LDA + cc);
        float x0 = silu_f(v.x);
        float x1 = silu_f(v.y);
        float x2 = silu_f(v.z);
        float x3 = silu_f(v.w);
        float s = x0 + x1 + x2 + x3;
        float q = x0 * x0 + x1 * x1 + x2 * x2 + x3 * x3;
        #pragma unroll
        for (int o = 16; o > 0; o >>= 1) {
            s += __shfl_xor_sync(0xffffffffu, s, o);
            q += __shfl_xor_sync(0xffffffffu, q, o);
        }
        float mean = s * (1.f / ND);
        float var  = q * (1.f / ND) - mean * mean;
        float rstd = rsqrtf(var + 1e-5f);
        float4 gg = *(const float4*)(lng + cc);
        float4 bb = *(const float4*)(lnb + cc);
        float y0 = (x0 - mean) * rstd * gg.x + bb.x;
        float y1 = (x1 - mean) * rstd * gg.y + bb.y;
        float y2 = (x2 - mean) * rstd * gg.z + bb.z;
        float y3 = (x3 - mean) * rstd * gg.w + bb.w;
        float4 tg = *(float4*)(Ash + r * LDA + cc);
        *(float4*)(out2 + e * ND + cc) = make_float4(tg.x + y0, tg.y + y1, tg.z + y2, tg.w + y3);
    }
}

// ---------------------------------------------------------------------------
extern "C" void kernel_launch(void* const* d_in, const int* in_sizes, int n_in,
                              void* d_out, int out_size) {
    const float* bond = (const float*)d_in[0];
    const float* src  = (const float*)d_in[1];
    const float* tgt  = (const float*)d_in[2];
    const float* Ws2e = (const float*)d_in[3];
    const float* Wt2e = (const float*)d_in[4];
    const float* We2e = (const float*)d_in[5];
    const float* ln1g = (const float*)d_in[6];
    const float* ln1b = (const float*)d_in[7];
    const float* We2t = (const float*)d_in[8];
    const float* Wt2t = (const float*)d_in[9];
    const float* ln2g = (const float*)d_in[10];
    const float* ln2b = (const float*)d_in[11];
    const float* coef = (const float*)d_in[12];
    const int* so = (const int*)d_in[13];
    const int* to = (const int*)d_in[14];
    const int* eo = (const int*)d_in[15];

    float* out0 = (float*)d_out;                         // [B,E,D]
    float* out1 = out0 + (size_t)NB * NE * ND;           // [B,NS,D]
    float* out2 = out1 + (size_t)NB * NS_N * ND;         // [B,NT,D]

    cudaFuncSetAttribute(proj_kernel, cudaFuncAttributeMaxDynamicSharedMemorySize, SMEM_BYTES);
    cudaFuncSetAttribute(edge_kernel, cudaFuncAttributeMaxDynamicSharedMemorySize, SMEM_BYTES);
    cudaFuncSetAttribute(tgt_kernel,  cudaFuncAttributeMaxDynamicSharedMemorySize, SMEM_BYTES);

    // out1 = src (independent; overlaps with proj on copy engine path)
    cudaMemcpyAsync(out1, src, (size_t)NB * NS_N * ND * sizeof(float),
                    cudaMemcpyDeviceToDevice);

    const int mtiles = (NB * NS_N + 127) / 128;          // 313
    proj_kernel<<<dim3(mtiles, 2), 256, SMEM_BYTES>>>(src, tgt, Ws2e, Wt2e);
    edge_kernel<<<NB * NE / 128, 256, SMEM_BYTES>>>(bond, We2e, ln1g, ln1b, so, to, out0);
    gather_kernel<<<NB * NT_N, 128>>>(eo, coef);
    tgt_kernel<<<mtiles, 256, SMEM_BYTES>>>(tgt, We2t, Wt2t, ln2g, ln2b, out2);
}